// round 6
// baseline (speedup 1.0000x reference)
#include <cuda_runtime.h>
#include <cstdint>

// Encoder_12240656794040 — GraphSAGE encoder, HBM-streaming bound on weight.
// features: [100000, 128] f32
// weight:   [4096, 256, 128] f32  (536 MB streamed once — the roofline)
// nodes:    [4096] i32, neigh_idx: [4096,10] i32
// out:      [4096, 128] f32
//
// R3: warp-owns-32-columns GEMV, scalar loads, no cross-warp reduction,
//     <=32 regs -> 16 CTAs/SM (100% occ) to maximize in-flight DRAM loads.

#define FEAT 128
#define TWOF 256
#define EMB  128
#define NS   10

__global__ __launch_bounds__(128, 16)
void encoder_kernel(const float* __restrict__ features,
                    const float* __restrict__ weight,
                    const int*   __restrict__ nodes,
                    const int*   __restrict__ neigh,
                    float*       __restrict__ out)
{
    const int b    = blockIdx.x;
    const int t    = threadIdx.x;   // 0..127
    const int warp = t >> 5;
    const int lane = t & 31;

    __shared__ float comb[TWOF];

    // ---- Phase 1: build combined[256] in smem ----
    {
        const int sn = __ldg(&nodes[b]);
        comb[t] = __ldg(&features[(size_t)sn * FEAT + t]);

        float acc = 0.f;
        const int* ni = neigh + (size_t)b * NS;
        #pragma unroll
        for (int j = 0; j < NS; ++j) {
            const int n = __ldg(&ni[j]);
            acc += __ldg(&features[(size_t)n * FEAT + t]);
        }
        comb[FEAT + t] = acc * (1.0f / NS);
    }
    __syncthreads();

    // ---- Phase 2: GEMV. Warp w owns columns [32w, 32w+32). ----
    // Per i, each warp loads 128B contiguous; 4 warps cover the 512B row.
    const int col = (warp << 5) + lane;
    const float* __restrict__ Wp = weight + (size_t)b * TWOF * EMB + col;

    float acc = 0.f;
    #pragma unroll 8
    for (int i = 0; i < TWOF; ++i) {
        acc = fmaf(comb[i], __ldcs(&Wp[(size_t)i * EMB]), acc);
    }

    __stcs(&out[(size_t)b * EMB + col], fmaxf(acc, 0.f));
}

extern "C" void kernel_launch(void* const* d_in, const int* in_sizes, int n_in,
                              void* d_out, int out_size)
{
    const float* features = (const float*)d_in[0];
    const float* weight   = (const float*)d_in[1];
    const int*   nodes    = (const int*)d_in[2];
    const int*   neigh    = (const int*)d_in[3];
    float*       out      = (float*)d_out;

    const int batch = in_sizes[2];  // 4096
    encoder_kernel<<<batch, 128>>>(features, weight, nodes, neigh, out);
}

// round 7
// speedup vs baseline: 1.1303x; 1.1303x over previous
#include <cuda_runtime.h>
#include <cstdint>

// Encoder_12240656794040 — GraphSAGE encoder, HBM-streaming bound on weight.
// features: [100000, 128] f32
// weight:   [4096, 256, 128] f32  (536 MB streamed once — the roofline)
// nodes:    [4096] i32, neigh_idx: [4096,10] i32
// out:      [4096, 128] f32
//
// R4: R1 float4-GEMV shape + register prefetch of 8 weight rows per warp
//     issued BEFORE the gather/barrier, so DRAM stays fed through the
//     phase-1 dependent-gather window.

#define FEAT 128
#define TWOF 256
#define EMB  128
#define NS   10

__global__ __launch_bounds__(128, 6)
void encoder_kernel(const float* __restrict__ features,
                    const float* __restrict__ weight,
                    const int*   __restrict__ nodes,
                    const int*   __restrict__ neigh,
                    float*       __restrict__ out)
{
    const int b    = blockIdx.x;
    const int t    = threadIdx.x;   // 0..127
    const int warp = t >> 5;
    const int lane = t & 31;

    __shared__ float comb[TWOF];
    __shared__ float4 part[4][32];

    // ---- 0: index loads first (dependency root of the gather) ----
    const int sn = __ldg(&nodes[b]);
    int ni[NS];
    #pragma unroll
    for (int j = 0; j < NS; ++j)
        ni[j] = __ldg(&neigh[(size_t)b * NS + j]);

    // ---- 1: prefetch first 8 weight rows of this warp (independent of gather;
    //          these loads remain in flight across the barrier) ----
    const float4* __restrict__ W =
        reinterpret_cast<const float4*>(weight + (size_t)b * TWOF * EMB);
    float4 w[8];
    #pragma unroll
    for (int k = 0; k < 8; ++k)
        w[k] = __ldcs(&W[(warp + 4 * k) * (EMB / 4) + lane]);

    // ---- 2: gather combined[256] into smem ----
    comb[t] = __ldg(&features[(size_t)sn * FEAT + t]);
    {
        float acc = 0.f;
        #pragma unroll
        for (int j = 0; j < NS; ++j)
            acc += __ldg(&features[(size_t)ni[j] * FEAT + t]);
        comb[FEAT + t] = acc * (1.0f / NS);
    }
    __syncthreads();

    // ---- 3: GEMV. Warp w handles i = w, w+4, ..., w+252. ----
    float4 a = make_float4(0.f, 0.f, 0.f, 0.f);

    // consume prefetched rows (i = warp .. warp+28)
    #pragma unroll
    for (int k = 0; k < 8; ++k) {
        const float c = comb[warp + 4 * k];
        a.x = fmaf(c, w[k].x, a.x);
        a.y = fmaf(c, w[k].y, a.y);
        a.z = fmaf(c, w[k].z, a.z);
        a.w = fmaf(c, w[k].w, a.w);
    }

    // stream the remaining 56 rows per warp
    #pragma unroll 8
    for (int i = warp + 32; i < TWOF; i += 4) {
        const float  c  = comb[i];
        const float4 wv = __ldcs(&W[i * (EMB / 4) + lane]);
        a.x = fmaf(c, wv.x, a.x);
        a.y = fmaf(c, wv.y, a.y);
        a.z = fmaf(c, wv.z, a.z);
        a.w = fmaf(c, wv.w, a.w);
    }
    part[warp][lane] = a;
    __syncthreads();

    // ---- 4: cross-warp reduce + ReLU + store ----
    if (warp == 0) {
        float4 s  = part[0][lane];
        float4 p1 = part[1][lane];
        float4 p2 = part[2][lane];
        float4 p3 = part[3][lane];
        s.x += p1.x + p2.x + p3.x;
        s.y += p1.y + p2.y + p3.y;
        s.z += p1.z + p2.z + p3.z;
        s.w += p1.w + p2.w + p3.w;
        s.x = fmaxf(s.x, 0.f);
        s.y = fmaxf(s.y, 0.f);
        s.z = fmaxf(s.z, 0.f);
        s.w = fmaxf(s.w, 0.f);
        __stcs(&reinterpret_cast<float4*>(out)[(size_t)b * (EMB / 4) + lane], s);
    }
}

extern "C" void kernel_launch(void* const* d_in, const int* in_sizes, int n_in,
                              void* d_out, int out_size)
{
    const float* features = (const float*)d_in[0];
    const float* weight   = (const float*)d_in[1];
    const int*   nodes    = (const int*)d_in[2];
    const int*   neigh    = (const int*)d_in[3];
    float*       out      = (float*)d_out;

    const int batch = in_sizes[2];  // 4096
    encoder_kernel<<<batch, 128>>>(features, weight, nodes, neigh, out);
}